// round 1
// baseline (speedup 1.0000x reference)
#include <cuda_runtime.h>

#define BB 16
#define CC 192
#define HH 64
#define WW 64
#define LL (HH*WW)      // 4096
#define RR 12           // dt_rank
#define NK 14           // dt_rank + 2*d_state

// Scratch (no cudaMalloc allowed): xs = conv+silu activations, xdbl = x_proj output
__device__ float g_xs[(size_t)BB*CC*LL];     // 50.3 MB
__device__ float g_xdbl[(size_t)BB*NK*LL];   // 3.7 MB

// ---------------------------------------------------------------------------
// K1: depthwise 5x5 conv (cross-correlation, SAME/zero pad) + bias + SiLU
// One block per (b,c) 64x64 image. 68x68 zero-padded tile in smem.
// ---------------------------------------------------------------------------
__global__ __launch_bounds__(256) void conv_silu_kernel(
    const float* __restrict__ x,
    const float* __restrict__ cw,
    const float* __restrict__ cb)
{
    int bc = blockIdx.x;            // b*CC + c
    int c  = bc % CC;
    __shared__ float s[68 * 68];
    const float* img = x + (size_t)bc * LL;
    int tid = threadIdx.x;

    // load padded tile (coalesced; zeros outside)
    for (int idx = tid; idx < 68 * 68; idx += 256) {
        int yy = idx / 68, xx = idx % 68;
        int iy = yy - 2, ix = xx - 2;
        float v = 0.f;
        if (iy >= 0 && iy < HH && ix >= 0 && ix < WW) v = img[iy * WW + ix];
        s[idx] = v;
    }

    float w[25];
#pragma unroll
    for (int i = 0; i < 25; i++) w[i] = __ldg(&cw[c * 25 + i]);
    float bias = __ldg(&cb[c]);
    __syncthreads();

    int xcol = tid & 63;            // 0..63
    int y0   = (tid >> 6) * 16;     // 4 row-groups of 16
    float* dst = g_xs + (size_t)bc * LL;

    for (int y = y0; y < y0 + 16; y++) {
        float acc = bias;
#pragma unroll
        for (int dy = 0; dy < 5; dy++) {
#pragma unroll
            for (int dx = 0; dx < 5; dx++) {
                acc += s[(y + dy) * 68 + xcol + dx] * w[dy * 5 + dx];
            }
        }
        // SiLU
        float sig = 1.f / (1.f + __expf(-acc));
        dst[y * WW + xcol] = acc * sig;
    }
}

// ---------------------------------------------------------------------------
// K2: x_dbl[b,k,l] = sum_c x_proj_w[k,c] * xs[b,c,l]   (k = 0..13)
// One thread per l. Weights transposed+padded (c,16) in smem -> 4 bcast LDS.128
// per channel step. grid = (LL/256, BB).
// ---------------------------------------------------------------------------
__global__ __launch_bounds__(256) void xproj_kernel(const float* __restrict__ xw)
{
    __shared__ float sw[CC * 16];
    int tid = threadIdx.x;
    for (int i = tid; i < CC * 16; i += 256) sw[i] = 0.f;
    __syncthreads();
    for (int i = tid; i < NK * CC; i += 256) {
        int k = i / CC, c = i % CC;
        sw[c * 16 + k] = xw[i];
    }
    __syncthreads();

    int b = blockIdx.y;
    int l = blockIdx.x * 256 + tid;
    const float* xs = g_xs + (size_t)b * CC * LL + l;

    float acc[NK];
#pragma unroll
    for (int k = 0; k < NK; k++) acc[k] = 0.f;

#pragma unroll 4
    for (int c = 0; c < CC; c++) {
        float v = xs[(size_t)c * LL];
        const float4* wp = (const float4*)&sw[c * 16];
        float4 w0 = wp[0], w1 = wp[1], w2 = wp[2], w3 = wp[3];
        acc[0]  += w0.x * v; acc[1]  += w0.y * v; acc[2]  += w0.z * v; acc[3]  += w0.w * v;
        acc[4]  += w1.x * v; acc[5]  += w1.y * v; acc[6]  += w1.z * v; acc[7]  += w1.w * v;
        acc[8]  += w2.x * v; acc[9]  += w2.y * v; acc[10] += w2.z * v; acc[11] += w2.w * v;
        acc[12] += w3.x * v; acc[13] += w3.y * v;
    }

    float* od = g_xdbl + (size_t)b * NK * LL + l;
#pragma unroll
    for (int k = 0; k < NK; k++) od[(size_t)k * LL] = acc[k];
}

// ---------------------------------------------------------------------------
// K3: fused dt-projection + softplus + selective scan (d_state=1) + output.
// One block of 128 threads per (b,c); each thread owns 32 contiguous l's.
// Two-level scan: per-thread sequential compose -> block Hillis-Steele on
// affine maps (A,B) -> replay with carry.
// ---------------------------------------------------------------------------
#define TPB3 128
#define SEG  32

__global__ __launch_bounds__(TPB3) void scan_kernel(
    const float* __restrict__ dt_w,
    const float* __restrict__ dt_b,
    const float* __restrict__ A_logs,
    const float* __restrict__ Ds,
    float* __restrict__ out)
{
    int bc = blockIdx.x;
    int b = bc / CC, c = bc % CC;
    int t = threadIdx.x;

    const float* xs_row   = g_xs   + (size_t)bc * LL;
    const float* dts_base = g_xdbl + (size_t)b * NK * LL;
    const float* Bs_row   = dts_base + (size_t)RR * LL;        // row 12
    const float* Cs_row   = dts_base + (size_t)(RR + 1) * LL;  // row 13

    float w[RR];
#pragma unroll
    for (int r = 0; r < RR; r++) w[r] = __ldg(&dt_w[c * RR + r]);
    float bias = __ldg(&dt_b[c]);
    float A    = -__expf(__ldg(&A_logs[c]));
    float Dv   = __ldg(&Ds[c]);

    int l0 = t * SEG;

    // ---- delta = softplus(dt_w . dts + dt_b) ----
    float delta[SEG];
#pragma unroll
    for (int i = 0; i < SEG; i++) delta[i] = bias;
#pragma unroll
    for (int r = 0; r < RR; r++) {
        const float4* p = (const float4*)(dts_base + (size_t)r * LL + l0);
        float wr = w[r];
#pragma unroll
        for (int j = 0; j < SEG / 4; j++) {
            float4 v = p[j];
            delta[4 * j + 0] += wr * v.x;
            delta[4 * j + 1] += wr * v.y;
            delta[4 * j + 2] += wr * v.z;
            delta[4 * j + 3] += wr * v.w;
        }
    }
#pragma unroll
    for (int i = 0; i < SEG; i++) {
        float d0 = delta[i];
        delta[i] = (d0 > 20.f) ? d0 : log1pf(__expf(d0));
    }

    // ---- load xs segment ----
    float xv[SEG];
    {
        const float4* px = (const float4*)(xs_row + l0);
#pragma unroll
        for (int j = 0; j < SEG / 4; j++) {
            float4 v = px[j];
            xv[4 * j + 0] = v.x; xv[4 * j + 1] = v.y;
            xv[4 * j + 2] = v.z; xv[4 * j + 3] = v.w;
        }
    }

    // ---- per-thread segment composition: h_out = Aseg*h_in + Bseg ----
    float Aseg = 1.f, Bseg = 0.f;
    const float4* pb = (const float4*)(Bs_row + l0);
#pragma unroll
    for (int j = 0; j < SEG / 4; j++) {
        float4 bv = pb[j];
        float bsv[4] = {bv.x, bv.y, bv.z, bv.w};
#pragma unroll
        for (int k = 0; k < 4; k++) {
            int i = 4 * j + k;
            float a  = __expf(A * delta[i]);
            float bt = delta[i] * bsv[k] * xv[i];
            Aseg = a * Aseg;
            Bseg = a * Bseg + bt;
        }
    }

    // ---- block scan of affine maps (Hillis-Steele, 7 steps) ----
    __shared__ float sA[TPB3], sB[TPB3];
    sA[t] = Aseg; sB[t] = Bseg;
    __syncthreads();
    for (int off = 1; off < TPB3; off <<= 1) {
        float a2 = sA[t], b2 = sB[t];
        float a1 = 1.f, b1 = 0.f;
        if (t >= off) { a1 = sA[t - off]; b1 = sB[t - off]; }
        __syncthreads();
        if (t >= off) { sA[t] = a2 * a1; sB[t] = a2 * b1 + b2; }
        __syncthreads();
    }
    float h = (t == 0) ? 0.f : sB[t - 1];

    // ---- replay with carry, produce y ----
    float* out_row = out + (size_t)bc * LL + l0;
    const float4* pc = (const float4*)(Cs_row + l0);
#pragma unroll
    for (int j = 0; j < SEG / 4; j++) {
        float4 bv = pb[j];
        float4 cv = pc[j];
        float bsv[4] = {bv.x, bv.y, bv.z, bv.w};
        float csv[4] = {cv.x, cv.y, cv.z, cv.w};
        float yo[4];
#pragma unroll
        for (int k = 0; k < 4; k++) {
            int i = 4 * j + k;
            float a = __expf(A * delta[i]);
            h = a * h + delta[i] * bsv[k] * xv[i];
            yo[k] = h * csv[k] + xv[i] * Dv;
        }
        float4 o4 = make_float4(yo[0], yo[1], yo[2], yo[3]);
        ((float4*)out_row)[j] = o4;
    }
}

// ---------------------------------------------------------------------------
extern "C" void kernel_launch(void* const* d_in, const int* in_sizes, int n_in,
                              void* d_out, int out_size)
{
    const float* x        = (const float*)d_in[0];
    const float* conv_w   = (const float*)d_in[1];
    const float* conv_b   = (const float*)d_in[2];
    const float* x_proj_w = (const float*)d_in[3];
    const float* dt_w     = (const float*)d_in[4];
    const float* dt_b     = (const float*)d_in[5];
    const float* A_logs   = (const float*)d_in[6];
    const float* Ds       = (const float*)d_in[7];
    float* out = (float*)d_out;

    conv_silu_kernel<<<BB * CC, 256>>>(x, conv_w, conv_b);
    xproj_kernel<<<dim3(LL / 256, BB), 256>>>(x_proj_w);
    scan_kernel<<<BB * CC, TPB3>>>(dt_w, dt_b, A_logs, Ds, out);
}

// round 2
// speedup vs baseline: 2.1893x; 2.1893x over previous
#include <cuda_runtime.h>

#define BB 16
#define CC 192
#define HH 64
#define WW 64
#define LL (HH*WW)      // 4096
#define RR 12           // dt_rank
#define NK 14           // dt_rank + 2*d_state

// Scratch (no cudaMalloc allowed)
__device__ float g_xs[(size_t)BB*CC*LL];      // 50.3 MB  conv+SiLU output
__device__ float g_delta[(size_t)BB*CC*LL];   // 50.3 MB  softplus(dt-proj)
__device__ float g_bc[(size_t)BB*2*LL];       // 0.5 MB   Bs, Cs rows

// ---------------------------------------------------------------------------
// K1: depthwise 5x5 conv (cross-correlation, SAME) + bias + SiLU
// One block per (b,c) 64x64 image; 68x68 padded smem tile; rolling 5x5
// register window -> 5 LDS per output instead of 25.
// ---------------------------------------------------------------------------
__global__ __launch_bounds__(256) void conv_silu_kernel(
    const float* __restrict__ x,
    const float* __restrict__ cw,
    const float* __restrict__ cb)
{
    int bc = blockIdx.x;            // b*CC + c
    int c  = bc % CC;
    __shared__ float s[68 * 68];
    const float* img = x + (size_t)bc * LL;
    int tid = threadIdx.x;

    for (int idx = tid; idx < 68 * 68; idx += 256) {
        int yy = idx / 68, xx = idx % 68;
        int iy = yy - 2, ix = xx - 2;
        float v = 0.f;
        if (iy >= 0 && iy < HH && ix >= 0 && ix < WW) v = img[iy * WW + ix];
        s[idx] = v;
    }

    float w[25];
#pragma unroll
    for (int i = 0; i < 25; i++) w[i] = __ldg(&cw[c * 25 + i]);
    float bias = __ldg(&cb[c]);
    __syncthreads();

    int xcol = tid & 63;            // 0..63 (warp-contiguous)
    int y0   = (tid >> 6) * 16;     // 4 row-groups of 16
    float* dst = g_xs + (size_t)bc * LL;

    // rolling window: win[dy][dx] = s[(y+dy)*68 + xcol+dx]
    float win[5][5];
#pragma unroll
    for (int dy = 0; dy < 4; dy++)
#pragma unroll
        for (int dx = 0; dx < 5; dx++)
            win[dy][dx] = s[(y0 + dy) * 68 + xcol + dx];

#pragma unroll
    for (int i = 0; i < 16; i++) {
        int y = y0 + i;
        // load new bottom row
#pragma unroll
        for (int dx = 0; dx < 5; dx++)
            win[4][dx] = s[(y + 4) * 68 + xcol + dx];

        float acc = bias;
#pragma unroll
        for (int dy = 0; dy < 5; dy++)
#pragma unroll
            for (int dx = 0; dx < 5; dx++)
                acc += win[dy][dx] * w[dy * 5 + dx];

        float e = __expf(-acc);
        dst[y * WW + xcol] = __fdividef(acc, 1.f + e);

        // shift rows up (renamed away by ptxas under full unroll)
#pragma unroll
        for (int dy = 0; dy < 4; dy++)
#pragma unroll
            for (int dx = 0; dx < 5; dx++)
                win[dy][dx] = win[dy + 1][dx];
    }
}

// ---------------------------------------------------------------------------
// K2: fused x_proj + dt-projection + softplus.
//   dts[0..11], Bs, Cs computed per l; then delta[b,c,l] for ALL 192 c
//   written coalesced (kills the 600MB dts re-read in the scan kernel).
// grid = (LL/128, BB), 128 threads; each thread owns one l.
// ---------------------------------------------------------------------------
__global__ __launch_bounds__(128) void xproj_delta_kernel(
    const float* __restrict__ xw,     // (14, C)
    const float* __restrict__ dtw,    // (C, 12)
    const float* __restrict__ dtb)    // (C,)
{
    __shared__ float sw[CC * 16];     // x_proj_w transposed (c,16) padded
    __shared__ float sdt[CC * RR];    // dt_w rows (c-major, 48B stride)
    __shared__ float sdb[CC];
    int tid = threadIdx.x;
    for (int i = tid; i < CC * 16; i += 128) sw[i] = 0.f;
    __syncthreads();
    for (int i = tid; i < NK * CC; i += 128) {
        int k = i / CC, c = i % CC;
        sw[c * 16 + k] = xw[i];
    }
    for (int i = tid; i < CC * RR; i += 128) sdt[i] = dtw[i];
    for (int i = tid; i < CC; i += 128) sdb[i] = dtb[i];
    __syncthreads();

    int b = blockIdx.y;
    int l = blockIdx.x * 128 + tid;
    const float* xs = g_xs + (size_t)b * CC * LL + l;

    float acc[NK];
#pragma unroll
    for (int k = 0; k < NK; k++) acc[k] = 0.f;

#pragma unroll 4
    for (int c = 0; c < CC; c++) {
        float v = xs[(size_t)c * LL];
        const float4* wp = (const float4*)&sw[c * 16];
        float4 w0 = wp[0], w1 = wp[1], w2 = wp[2], w3 = wp[3];
        acc[0]  += w0.x * v; acc[1]  += w0.y * v; acc[2]  += w0.z * v; acc[3]  += w0.w * v;
        acc[4]  += w1.x * v; acc[5]  += w1.y * v; acc[6]  += w1.z * v; acc[7]  += w1.w * v;
        acc[8]  += w2.x * v; acc[9]  += w2.y * v; acc[10] += w2.z * v; acc[11] += w2.w * v;
        acc[12] += w3.x * v; acc[13] += w3.y * v;
    }

    // Bs, Cs
    float* bcp = g_bc + (size_t)b * 2 * LL + l;
    bcp[0]  = acc[12];
    bcp[LL] = acc[13];

    // delta[c] = softplus(dt_w[c,:] . dts + dt_b[c]) for all c
    float* dl = g_delta + (size_t)b * CC * LL + l;
#pragma unroll 2
    for (int c = 0; c < CC; c++) {
        const float4* dwp = (const float4*)&sdt[c * RR];  // 3 bcast LDS.128
        float4 d0 = dwp[0], d1 = dwp[1], d2 = dwp[2];
        float d = sdb[c];
        d += d0.x * acc[0] + d0.y * acc[1] + d0.z * acc[2] + d0.w * acc[3];
        d += d1.x * acc[4] + d1.y * acc[5] + d1.z * acc[6] + d1.w * acc[7];
        d += d2.x * acc[8] + d2.y * acc[9] + d2.z * acc[10] + d2.w * acc[11];
        // softplus via exp2/log2 (2 MUFU); guard large d
        float t  = __log2f(1.f + exp2f(d * 1.44269504f));
        float sp = (d > 20.f) ? d : t * 0.69314718f;
        dl[(size_t)c * LL] = sp;
    }
}

// ---------------------------------------------------------------------------
// K3: selective scan (d_state=1) + output combine.
// One block of 256 threads per (b,c); thread owns 16 contiguous l's.
// Warp-shuffle scan of affine maps + 8-entry smem carry.
// ---------------------------------------------------------------------------
#define TPB3 256
#define SEG  16

__global__ __launch_bounds__(TPB3) void scan_kernel(
    const float* __restrict__ A_logs,
    const float* __restrict__ Ds,
    float* __restrict__ out)
{
    int bc = blockIdx.x;
    int b = bc / CC, c = bc % CC;
    int t = threadIdx.x;
    int lane = t & 31, wid = t >> 5;

    const float* xs_row = g_xs    + (size_t)bc * LL;
    const float* dl_row = g_delta + (size_t)bc * LL;
    const float* Bs_row = g_bc + (size_t)b * 2 * LL;
    const float* Cs_row = Bs_row + LL;

    float A  = -__expf(__ldg(&A_logs[c]));
    float Dv = __ldg(&Ds[c]);
    float Al2 = A * 1.44269504f;     // a = exp2(Al2 * delta)

    int l0 = t * SEG;

    float delta[SEG], xv[SEG];
    {
        const float4* pd = (const float4*)(dl_row + l0);
        const float4* px = (const float4*)(xs_row + l0);
#pragma unroll
        for (int j = 0; j < SEG / 4; j++) {
            float4 d = pd[j], v = px[j];
            delta[4*j+0]=d.x; delta[4*j+1]=d.y; delta[4*j+2]=d.z; delta[4*j+3]=d.w;
            xv[4*j+0]=v.x; xv[4*j+1]=v.y; xv[4*j+2]=v.z; xv[4*j+3]=v.w;
        }
    }

    // per-thread segment compose: h_out = Aseg*h_in + Bseg
    float Aseg = 1.f, Bseg = 0.f;
    const float4* pb = (const float4*)(Bs_row + l0);
#pragma unroll
    for (int j = 0; j < SEG / 4; j++) {
        float4 bv = pb[j];
        float bsv[4] = {bv.x, bv.y, bv.z, bv.w};
#pragma unroll
        for (int k = 0; k < 4; k++) {
            int i = 4 * j + k;
            float a  = exp2f(Al2 * delta[i]);
            float bt = delta[i] * bsv[k] * xv[i];
            Aseg = a * Aseg;
            Bseg = fmaf(a, Bseg, bt);
        }
    }

    // warp inclusive scan (compose earlier-first)
#pragma unroll
    for (int off = 1; off < 32; off <<= 1) {
        float aU = __shfl_up_sync(0xffffffffu, Aseg, off);
        float bU = __shfl_up_sync(0xffffffffu, Bseg, off);
        if (lane >= off) { Bseg = fmaf(Aseg, bU, Bseg); Aseg *= aU; }
    }
    __shared__ float swA[TPB3/32], swB[TPB3/32];
    if (lane == 31) { swA[wid] = Aseg; swB[wid] = Bseg; }
    // lane-exclusive within warp
    float aEx = __shfl_up_sync(0xffffffffu, Aseg, 1);
    float bEx = __shfl_up_sync(0xffffffffu, Bseg, 1);
    if (lane == 0) { aEx = 1.f; bEx = 0.f; }
    __syncthreads();
    // carry over preceding warps (h0 = 0 so only B matters)
    float Bc = 0.f;
    for (int wp = 0; wp < wid; wp++) Bc = fmaf(swA[wp], Bc, swB[wp]);
    float h = fmaf(aEx, Bc, bEx);   // state entering this thread's segment

    // replay with carry, produce y
    float* out_row = out + (size_t)bc * LL + l0;
    const float4* pc = (const float4*)(Cs_row + l0);
#pragma unroll
    for (int j = 0; j < SEG / 4; j++) {
        float4 bv = pb[j];
        float4 cv = pc[j];
        float bsv[4] = {bv.x, bv.y, bv.z, bv.w};
        float csv[4] = {cv.x, cv.y, cv.z, cv.w};
        float yo[4];
#pragma unroll
        for (int k = 0; k < 4; k++) {
            int i = 4 * j + k;
            float a = exp2f(Al2 * delta[i]);
            h = fmaf(a, h, delta[i] * bsv[k] * xv[i]);
            yo[k] = fmaf(h, csv[k], xv[i] * Dv);
        }
        ((float4*)out_row)[j] = make_float4(yo[0], yo[1], yo[2], yo[3]);
    }
}

// ---------------------------------------------------------------------------
extern "C" void kernel_launch(void* const* d_in, const int* in_sizes, int n_in,
                              void* d_out, int out_size)
{
    const float* x        = (const float*)d_in[0];
    const float* conv_w   = (const float*)d_in[1];
    const float* conv_b   = (const float*)d_in[2];
    const float* x_proj_w = (const float*)d_in[3];
    const float* dt_w     = (const float*)d_in[4];
    const float* dt_b     = (const float*)d_in[5];
    const float* A_logs   = (const float*)d_in[6];
    const float* Ds       = (const float*)d_in[7];
    float* out = (float*)d_out;

    conv_silu_kernel<<<BB * CC, 256>>>(x, conv_w, conv_b);
    xproj_delta_kernel<<<dim3(LL / 128, BB), 128>>>(x_proj_w, dt_w, dt_b);
    scan_kernel<<<BB * CC, TPB3>>>(A_logs, Ds, out);
}